// round 2
// baseline (speedup 1.0000x reference)
#include <cuda_runtime.h>
#include <cstdint>

#define HID  512
#define BATCH 4
#define SEQ  4096

// Scratch (static device globals; allocation-free per harness rules)
__device__ float g_qkv[(size_t)3 * BATCH * SEQ * HID];          // 96 MB: q | k | v
__device__ float g_scores[(size_t)BATCH * SEQ * SEQ];           // 256 MB

// ---------------------------------------------------------------------------
// tf32 helpers
// ---------------------------------------------------------------------------
__device__ __forceinline__ uint32_t f2tf32(float f) {
    uint32_t r;
    asm("cvt.rna.tf32.f32 %0, %1;" : "=r"(r) : "f"(f));
    return r;
}

__device__ __forceinline__ void mma8(float c[4],
                                     uint32_t a0, uint32_t a1, uint32_t a2, uint32_t a3,
                                     uint32_t b0, uint32_t b1) {
    asm volatile(
        "mma.sync.aligned.m16n8k8.row.col.f32.tf32.tf32.f32 "
        "{%0,%1,%2,%3}, {%4,%5,%6,%7}, {%8,%9}, {%0,%1,%2,%3};\n"
        : "+f"(c[0]), "+f"(c[1]), "+f"(c[2]), "+f"(c[3])
        : "r"(a0), "r"(a1), "r"(a2), "r"(a3), "r"(b0), "r"(b1));
}

// Split a float into tf32 hi + tf32 lo (3xtf32 trick -> ~fp32 accuracy)
__device__ __forceinline__ void split4(const float4 v, uint4& hi, uint4& lo) {
    uint32_t hx = f2tf32(v.x), hy = f2tf32(v.y), hz = f2tf32(v.z), hw = f2tf32(v.w);
    hi = make_uint4(hx, hy, hz, hw);
    lo = make_uint4(f2tf32(v.x - __uint_as_float(hx)),
                    f2tf32(v.y - __uint_as_float(hy)),
                    f2tf32(v.z - __uint_as_float(hz)),
                    f2tf32(v.w - __uint_as_float(hw)));
}

// ---------------------------------------------------------------------------
// Fragment-major shared layouts.
// A tile 128x16 per stage:  idx = ((m16*2 + ks8)*32 + lane)*4 + w
//   lane = lr*4+lc;  w: 0=(lr,lc) 1=(lr+8,lc) 2=(lr,lc+4) 3=(lr+8,lc+4)
//   -> each thread's 4 mma A-regs are one 16B-aligned LDS.128
// B tile 64x16 per stage:   idx = ((n8*2 + ks8)*32 + lane)*2 + w
//   w: 0=(n=lr,k=lc) 1=(n=lr,k=lc+4)   -> one LDS.64 per thread
// ---------------------------------------------------------------------------
// 48KB static smem total (2 buffers x (A hi/lo 8KB each + B hi/lo 4KB each))

__device__ __forceinline__ void compute_stage(
    const uint32_t* __restrict__ Ah_, const uint32_t* __restrict__ Al_,
    const uint32_t* __restrict__ Bh_, const uint32_t* __restrict__ Bl_,
    float acc[2][4][4], int m16base, int n8base, int lane)
{
#pragma unroll
    for (int ks8 = 0; ks8 < 2; ks8++) {
        uint4 Ah[2], Al[2];
#pragma unroll
        for (int mi = 0; mi < 2; mi++) {
            int off = (((m16base + mi) * 2 + ks8) * 32 + lane) * 4;
            Ah[mi] = *(const uint4*)(Ah_ + off);
            Al[mi] = *(const uint4*)(Al_ + off);
        }
#pragma unroll
        for (int ni = 0; ni < 4; ni++) {
            int off = (((n8base + ni) * 2 + ks8) * 32 + lane) * 2;
            uint2 Bh = *(const uint2*)(Bh_ + off);
            uint2 Bl = *(const uint2*)(Bl_ + off);
#pragma unroll
            for (int mi = 0; mi < 2; mi++) {
                mma8(acc[mi][ni], Ah[mi].x, Ah[mi].y, Ah[mi].z, Ah[mi].w, Bh.x, Bh.y);
                mma8(acc[mi][ni], Ah[mi].x, Ah[mi].y, Ah[mi].z, Ah[mi].w, Bl.x, Bl.y);
                mma8(acc[mi][ni], Al[mi].x, Al[mi].y, Al[mi].z, Al[mi].w, Bh.x, Bh.y);
            }
        }
    }
}

// ---------------------------------------------------------------------------
// GEMM NT: C[m,n] = sum_k A[m,k] * B[n,k]  (both K-major)
// BM=128, BN=64, BK=16, 256 threads (4x2 warps of 32x32), double-buffered.
// ---------------------------------------------------------------------------
__global__ void __launch_bounds__(256) gemm_nt(
    const float* __restrict__ A, const float* __restrict__ B, float* __restrict__ C,
    int lda, int ldb, int ldc, int Kdim,
    long long sA_, long long sB_, long long sC_)
{
    __shared__ __align__(16) uint32_t sAhi[2][2048], sAlo[2][2048];
    __shared__ __align__(16) uint32_t sBhi[2][1024], sBlo[2][1024];

    const float* Ag = A + (long long)blockIdx.z * sA_ + (long long)blockIdx.y * 128 * lda;
    const float* Bg = B + (long long)blockIdx.z * sB_ + (long long)blockIdx.x * 64 * ldb;
    float*       Cg = C + (long long)blockIdx.z * sC_ + (long long)blockIdx.y * 128 * ldc
                        + (long long)blockIdx.x * 64;

    const int tid  = threadIdx.x;
    const int warp = tid >> 5, lane = tid & 31;
    const int wm = (warp >> 1) * 32, wn = (warp & 1) * 32;
    const int m16base = wm >> 4, n8base = wn >> 3;
    const int lr = lane >> 2, lc = lane & 3;

    // staging coords
    const int ra0 = tid >> 2,            ca0 = (tid & 3) * 4;       // A row 0..63
    const int ra1 = (tid + 256) >> 2,    ca1 = (tid & 3) * 4;       // A row 64..127
    const int rb  = tid >> 2,            cb  = (tid & 3) * 4;       // B row 0..63

    float acc[2][4][4] = {};
    float4 va0, va1, vb;

    auto load_gmem = [&](int k0) {
        va0 = *(const float4*)(Ag + (long long)ra0 * lda + k0 + ca0);
        va1 = *(const float4*)(Ag + (long long)ra1 * lda + k0 + ca1);
        vb  = *(const float4*)(Bg + (long long)rb  * ldb + k0 + cb);
    };
    auto store_smem = [&](int buf) {
        uint4 hi, lo;
        // A part 0
        {
            split4(va0, hi, lo);
            int base = (((ra0 >> 4) * 2 + (ca0 >> 3)) * 32 + (ra0 & 7) * 4) * 4
                       + ((ra0 >> 3) & 1) + 2 * ((ca0 >> 2) & 1);
            sAhi[buf][base + 0]  = hi.x; sAhi[buf][base + 4]  = hi.y;
            sAhi[buf][base + 8]  = hi.z; sAhi[buf][base + 12] = hi.w;
            sAlo[buf][base + 0]  = lo.x; sAlo[buf][base + 4]  = lo.y;
            sAlo[buf][base + 8]  = lo.z; sAlo[buf][base + 12] = lo.w;
        }
        // A part 1
        {
            split4(va1, hi, lo);
            int base = (((ra1 >> 4) * 2 + (ca1 >> 3)) * 32 + (ra1 & 7) * 4) * 4
                       + ((ra1 >> 3) & 1) + 2 * ((ca1 >> 2) & 1);
            sAhi[buf][base + 0]  = hi.x; sAhi[buf][base + 4]  = hi.y;
            sAhi[buf][base + 8]  = hi.z; sAhi[buf][base + 12] = hi.w;
            sAlo[buf][base + 0]  = lo.x; sAlo[buf][base + 4]  = lo.y;
            sAlo[buf][base + 8]  = lo.z; sAlo[buf][base + 12] = lo.w;
        }
        // B (K-major rows = n)
        {
            split4(vb, hi, lo);
            int base = (((rb >> 3) * 2 + (cb >> 3)) * 32 + (rb & 7) * 4) * 2
                       + ((cb >> 2) & 1);
            sBhi[buf][base + 0] = hi.x; sBhi[buf][base + 2] = hi.y;
            sBhi[buf][base + 4] = hi.z; sBhi[buf][base + 6] = hi.w;
            sBlo[buf][base + 0] = lo.x; sBlo[buf][base + 2] = lo.y;
            sBlo[buf][base + 4] = lo.z; sBlo[buf][base + 6] = lo.w;
        }
    };

    load_gmem(0);
    store_smem(0);
    __syncthreads();

    int buf = 0;
    for (int k0 = 0; k0 < Kdim; k0 += 16) {
        bool more = (k0 + 16) < Kdim;
        if (more) load_gmem(k0 + 16);
        compute_stage(sAhi[buf], sAlo[buf], sBhi[buf], sBlo[buf],
                      acc, m16base, n8base, lane);
        if (more) {
            store_smem(buf ^ 1);
            __syncthreads();
            buf ^= 1;
        }
    }

#pragma unroll
    for (int mi = 0; mi < 2; mi++)
#pragma unroll
        for (int ni = 0; ni < 4; ni++) {
            int rr = wm + mi * 16 + lr;
            int cc = wn + ni * 8 + lc * 2;
            *(float2*)(Cg + (long long)rr * ldc + cc)       = make_float2(acc[mi][ni][0], acc[mi][ni][1]);
            *(float2*)(Cg + (long long)(rr + 8) * ldc + cc) = make_float2(acc[mi][ni][2], acc[mi][ni][3]);
        }
}

// ---------------------------------------------------------------------------
// GEMM NN: C[m,n] = sum_k A[m,k] * B[k,n]  (B N-contiguous). Used for O = P V.
// ---------------------------------------------------------------------------
__global__ void __launch_bounds__(256) gemm_nn(
    const float* __restrict__ A, const float* __restrict__ B, float* __restrict__ C,
    int lda, int ldb, int ldc, int Kdim,
    long long sA_, long long sB_, long long sC_)
{
    __shared__ __align__(16) uint32_t sAhi[2][2048], sAlo[2][2048];
    __shared__ __align__(16) uint32_t sBhi[2][1024], sBlo[2][1024];

    const float* Ag = A + (long long)blockIdx.z * sA_ + (long long)blockIdx.y * 128 * lda;
    const float* Bg = B + (long long)blockIdx.z * sB_ + (long long)blockIdx.x * 64;
    float*       Cg = C + (long long)blockIdx.z * sC_ + (long long)blockIdx.y * 128 * ldc
                        + (long long)blockIdx.x * 64;

    const int tid  = threadIdx.x;
    const int warp = tid >> 5, lane = tid & 31;
    const int wm = (warp >> 1) * 32, wn = (warp & 1) * 32;
    const int m16base = wm >> 4, n8base = wn >> 3;
    const int lr = lane >> 2, lc = lane & 3;

    const int ra0 = tid >> 2,         ca0 = (tid & 3) * 4;
    const int ra1 = (tid + 256) >> 2, ca1 = (tid & 3) * 4;
    const int rbn = tid >> 4;                 // k row 0..15
    const int cbn = (tid & 15) * 4;           // n col 0..60

    float acc[2][4][4] = {};
    float4 va0, va1, vb;

    auto load_gmem = [&](int k0) {
        va0 = *(const float4*)(Ag + (long long)ra0 * lda + k0 + ca0);
        va1 = *(const float4*)(Ag + (long long)ra1 * lda + k0 + ca1);
        vb  = *(const float4*)(Bg + (long long)(k0 + rbn) * ldb + cbn);
    };
    auto store_smem = [&](int buf) {
        uint4 hi, lo;
        {
            split4(va0, hi, lo);
            int base = (((ra0 >> 4) * 2 + (ca0 >> 3)) * 32 + (ra0 & 7) * 4) * 4
                       + ((ra0 >> 3) & 1) + 2 * ((ca0 >> 2) & 1);
            sAhi[buf][base + 0]  = hi.x; sAhi[buf][base + 4]  = hi.y;
            sAhi[buf][base + 8]  = hi.z; sAhi[buf][base + 12] = hi.w;
            sAlo[buf][base + 0]  = lo.x; sAlo[buf][base + 4]  = lo.y;
            sAlo[buf][base + 8]  = lo.z; sAlo[buf][base + 12] = lo.w;
        }
        {
            split4(va1, hi, lo);
            int base = (((ra1 >> 4) * 2 + (ca1 >> 3)) * 32 + (ra1 & 7) * 4) * 4
                       + ((ra1 >> 3) & 1) + 2 * ((ca1 >> 2) & 1);
            sAhi[buf][base + 0]  = hi.x; sAhi[buf][base + 4]  = hi.y;
            sAhi[buf][base + 8]  = hi.z; sAhi[buf][base + 12] = hi.w;
            sAlo[buf][base + 0]  = lo.x; sAlo[buf][base + 4]  = lo.y;
            sAlo[buf][base + 8]  = lo.z; sAlo[buf][base + 12] = lo.w;
        }
        // B element (k=rbn, n=cbn+e): n8=cbn>>3, lr=(cbn&7)+e, lc=rbn&3,
        // kh=(rbn>>2)&1, ks8=rbn>>3 ; lane = lr*4+lc -> addr stride 8 per e
        {
            split4(vb, hi, lo);
            int base = (((cbn >> 3) * 2 + (rbn >> 3)) * 32 + (cbn & 7) * 4 + (rbn & 3)) * 2
                       + ((rbn >> 2) & 1);
            sBhi[buf][base + 0]  = hi.x; sBhi[buf][base + 8]  = hi.y;
            sBhi[buf][base + 16] = hi.z; sBhi[buf][base + 24] = hi.w;
            sBlo[buf][base + 0]  = lo.x; sBlo[buf][base + 8]  = lo.y;
            sBlo[buf][base + 16] = lo.z; sBlo[buf][base + 24] = lo.w;
        }
    };

    load_gmem(0);
    store_smem(0);
    __syncthreads();

    int buf = 0;
    for (int k0 = 0; k0 < Kdim; k0 += 16) {
        bool more = (k0 + 16) < Kdim;
        if (more) load_gmem(k0 + 16);
        compute_stage(sAhi[buf], sAlo[buf], sBhi[buf], sBlo[buf],
                      acc, m16base, n8base, lane);
        if (more) {
            store_smem(buf ^ 1);
            __syncthreads();
            buf ^= 1;
        }
    }

#pragma unroll
    for (int mi = 0; mi < 2; mi++)
#pragma unroll
        for (int ni = 0; ni < 4; ni++) {
            int rr = wm + mi * 16 + lr;
            int cc = wn + ni * 8 + lc * 2;
            *(float2*)(Cg + (long long)rr * ldc + cc)       = make_float2(acc[mi][ni][0], acc[mi][ni][1]);
            *(float2*)(Cg + (long long)(rr + 8) * ldc + cc) = make_float2(acc[mi][ni][2], acc[mi][ni][3]);
        }
}

// ---------------------------------------------------------------------------
// Row softmax over SEQ=4096, with /sqrt(H) scale folded in.
// ---------------------------------------------------------------------------
__global__ void __launch_bounds__(256) softmax_kernel(float* __restrict__ S, float scale) {
    long long row = blockIdx.x;
    float* p = S + row * (long long)SEQ;
    const int tid = threadIdx.x;

    float4 v[4];
    float m = -3.4e38f;
#pragma unroll
    for (int i = 0; i < 4; i++) {
        v[i] = ((const float4*)p)[tid + i * 256];
        m = fmaxf(m, fmaxf(fmaxf(v[i].x, v[i].y), fmaxf(v[i].z, v[i].w)));
    }

    __shared__ float red[8];
#pragma unroll
    for (int o = 16; o; o >>= 1) m = fmaxf(m, __shfl_xor_sync(0xffffffffu, m, o));
    if ((tid & 31) == 0) red[tid >> 5] = m;
    __syncthreads();
    m = red[0];
#pragma unroll
    for (int i = 1; i < 8; i++) m = fmaxf(m, red[i]);

    float sum = 0.f;
#pragma unroll
    for (int i = 0; i < 4; i++) {
        v[i].x = __expf((v[i].x - m) * scale);
        v[i].y = __expf((v[i].y - m) * scale);
        v[i].z = __expf((v[i].z - m) * scale);
        v[i].w = __expf((v[i].w - m) * scale);
        sum += (v[i].x + v[i].y) + (v[i].z + v[i].w);
    }
#pragma unroll
    for (int o = 16; o; o >>= 1) sum += __shfl_xor_sync(0xffffffffu, sum, o);
    __syncthreads();
    if ((tid & 31) == 0) red[tid >> 5] = sum;
    __syncthreads();
    float tot = 0.f;
#pragma unroll
    for (int i = 0; i < 8; i++) tot += red[i];
    float inv = 1.0f / tot;

#pragma unroll
    for (int i = 0; i < 4; i++) {
        v[i].x *= inv; v[i].y *= inv; v[i].z *= inv; v[i].w *= inv;
        ((float4*)p)[tid + i * 256] = v[i];
    }
}

// ---------------------------------------------------------------------------
// Launcher
// ---------------------------------------------------------------------------
extern "C" void kernel_launch(void* const* d_in, const int* in_sizes, int n_in,
                              void* d_out, int out_size) {
    const float* x  = (const float*)d_in[0];
    const float* Wq = (const float*)d_in[1];
    const float* Wk = (const float*)d_in[2];
    const float* Wv = (const float*)d_in[3];
    float* out = (float*)d_out;

    float *qp, *sp;
    cudaGetSymbolAddress((void**)&qp, g_qkv);
    cudaGetSymbolAddress((void**)&sp, g_scores);
    float* kp = qp + (long long)BATCH * SEQ * HID;
    float* vp = kp + (long long)BATCH * SEQ * HID;

    dim3 blk(256);

    // 1) QKV projections: y = x W^T   (M=16384, N=512, K=512)
    dim3 gq(HID / 64, (BATCH * SEQ) / 128, 1);
    gemm_nt<<<gq, blk>>>(x, Wq, qp, HID, HID, HID, HID, 0, 0, 0);
    gemm_nt<<<gq, blk>>>(x, Wk, kp, HID, HID, HID, HID, 0, 0, 0);
    gemm_nt<<<gq, blk>>>(x, Wv, vp, HID, HID, HID, HID, 0, 0, 0);

    // 2) S = Q K^T   (batched: M=N=4096, K=512)
    dim3 gs(SEQ / 64, SEQ / 128, BATCH);
    gemm_nt<<<gs, blk>>>(qp, kp, sp, HID, HID, SEQ, HID,
                         (long long)SEQ * HID, (long long)SEQ * HID, (long long)SEQ * SEQ);

    // 3) softmax rows with 1/sqrt(H) scale
    softmax_kernel<<<BATCH * SEQ, 256>>>(sp, 0.044194173824159216f);

    // 4) O = P V   (M=4096, N=512, K=4096, batched)
    dim3 gp(HID / 64, SEQ / 128, BATCH);
    gemm_nn<<<gp, blk>>>(sp, vp, out, SEQ, HID, HID, SEQ,
                         (long long)SEQ * SEQ, (long long)SEQ * HID, (long long)SEQ * HID);
}

// round 3
// speedup vs baseline: 1.9910x; 1.9910x over previous
#include <cuda_runtime.h>
#include <cstdint>

#define HID  512
#define BATCH 4
#define SEQ  4096

// Scratch (static device globals; allocation-free per harness rules)
__device__ float g_qkv[(size_t)3 * BATCH * SEQ * HID];          // 96 MB: q | k | v
__device__ float g_scores[(size_t)BATCH * SEQ * SEQ];           // 256 MB

// ---------------------------------------------------------------------------
// tf32 helpers
// ---------------------------------------------------------------------------
__device__ __forceinline__ uint32_t f2tf32(float f) {
    uint32_t r;
    asm("cvt.rna.tf32.f32 %0, %1;" : "=r"(r) : "f"(f));
    return r;
}

__device__ __forceinline__ void mma8(float c[4],
                                     uint32_t a0, uint32_t a1, uint32_t a2, uint32_t a3,
                                     uint32_t b0, uint32_t b1) {
    asm volatile(
        "mma.sync.aligned.m16n8k8.row.col.f32.tf32.tf32.f32 "
        "{%0,%1,%2,%3}, {%4,%5,%6,%7}, {%8,%9}, {%0,%1,%2,%3};\n"
        : "+f"(c[0]), "+f"(c[1]), "+f"(c[2]), "+f"(c[3])
        : "r"(a0), "r"(a1), "r"(a2), "r"(a3), "r"(b0), "r"(b1));
}

// Split a float into tf32 hi + tf32 lo (3xtf32 trick -> ~fp32 accuracy)
__device__ __forceinline__ void split4(const float4 v, uint4& hi, uint4& lo) {
    uint32_t hx = f2tf32(v.x), hy = f2tf32(v.y), hz = f2tf32(v.z), hw = f2tf32(v.w);
    hi = make_uint4(hx, hy, hz, hw);
    lo = make_uint4(f2tf32(v.x - __uint_as_float(hx)),
                    f2tf32(v.y - __uint_as_float(hy)),
                    f2tf32(v.z - __uint_as_float(hz)),
                    f2tf32(v.w - __uint_as_float(hw)));
}

// ---------------------------------------------------------------------------
// GEMM NT: C[m,n] = sum_k A[m,k] * B[n,k]  (both K-major)
// BM=128, BN=128, BK=16. 128 threads = 4 warps (2x2), warp tile 64x64.
// Round-1-proven conflict-free [row][20] layout, STS.128 staging.
// ---------------------------------------------------------------------------
__global__ void __launch_bounds__(128) gemm_nt(
    const float* __restrict__ A, const float* __restrict__ B, float* __restrict__ C,
    int lda, int ldb, int ldc, int Kdim,
    long long sA_, long long sB_, long long sC_)
{
    __shared__ __align__(16) uint32_t sAhi[128][20], sAlo[128][20];
    __shared__ __align__(16) uint32_t sBhi[128][20], sBlo[128][20];

    const float* Ag = A + (long long)blockIdx.z * sA_ + (long long)blockIdx.y * 128 * lda;
    const float* Bg = B + (long long)blockIdx.z * sB_ + (long long)blockIdx.x * 128 * ldb;
    float*       Cg = C + (long long)blockIdx.z * sC_ + (long long)blockIdx.y * 128 * ldc
                        + (long long)blockIdx.x * 128;

    const int tid  = threadIdx.x;
    const int warp = tid >> 5, lane = tid & 31;
    const int wm = (warp >> 1) * 64, wn = (warp & 1) * 64;
    const int lr = lane >> 2, lc = lane & 3;

    // staging coords: thread covers rows p*32 + (tid>>2), cols (tid&3)*4
    const int rs = tid >> 2;
    const int cs = (tid & 3) * 4;

    float acc[4][8][4] = {};

    for (int k0 = 0; k0 < Kdim; k0 += 16) {
        float4 va[4], vb[4];
#pragma unroll
        for (int p = 0; p < 4; p++) {
            va[p] = *(const float4*)(Ag + (long long)(rs + p * 32) * lda + k0 + cs);
            vb[p] = *(const float4*)(Bg + (long long)(rs + p * 32) * ldb + k0 + cs);
        }
        __syncthreads();
#pragma unroll
        for (int p = 0; p < 4; p++) {
            uint4 hi, lo;
            split4(va[p], hi, lo);
            *(uint4*)&sAhi[rs + p * 32][cs] = hi;
            *(uint4*)&sAlo[rs + p * 32][cs] = lo;
            split4(vb[p], hi, lo);
            *(uint4*)&sBhi[rs + p * 32][cs] = hi;
            *(uint4*)&sBlo[rs + p * 32][cs] = lo;
        }
        __syncthreads();

#pragma unroll
        for (int ks = 0; ks < 16; ks += 8) {
            uint32_t ah[4][4], al[4][4];
#pragma unroll
            for (int mi = 0; mi < 4; mi++) {
                int r0 = wm + mi * 16 + lr;
                ah[mi][0] = sAhi[r0    ][ks + lc    ];  al[mi][0] = sAlo[r0    ][ks + lc    ];
                ah[mi][1] = sAhi[r0 + 8][ks + lc    ];  al[mi][1] = sAlo[r0 + 8][ks + lc    ];
                ah[mi][2] = sAhi[r0    ][ks + lc + 4];  al[mi][2] = sAlo[r0    ][ks + lc + 4];
                ah[mi][3] = sAhi[r0 + 8][ks + lc + 4];  al[mi][3] = sAlo[r0 + 8][ks + lc + 4];
            }
#pragma unroll
            for (int ni = 0; ni < 8; ni++) {
                int n0 = wn + ni * 8 + lr;
                uint32_t bh0 = sBhi[n0][ks + lc], bh1 = sBhi[n0][ks + lc + 4];
                uint32_t bl0 = sBlo[n0][ks + lc], bl1 = sBlo[n0][ks + lc + 4];
#pragma unroll
                for (int mi = 0; mi < 4; mi++) {
                    mma8(acc[mi][ni], ah[mi][0], ah[mi][1], ah[mi][2], ah[mi][3], bh0, bh1);
                    mma8(acc[mi][ni], ah[mi][0], ah[mi][1], ah[mi][2], ah[mi][3], bl0, bl1);
                    mma8(acc[mi][ni], al[mi][0], al[mi][1], al[mi][2], al[mi][3], bh0, bh1);
                }
            }
        }
    }

#pragma unroll
    for (int mi = 0; mi < 4; mi++)
#pragma unroll
        for (int ni = 0; ni < 8; ni++) {
            int rr = wm + mi * 16 + lr;
            int cc = wn + ni * 8 + lc * 2;
            *(float2*)(Cg + (long long)rr * ldc + cc)       = make_float2(acc[mi][ni][0], acc[mi][ni][1]);
            *(float2*)(Cg + (long long)(rr + 8) * ldc + cc) = make_float2(acc[mi][ni][2], acc[mi][ni][3]);
        }
}

// ---------------------------------------------------------------------------
// GEMM NN: C[m,n] = sum_k A[m,k] * B[k,n]  (B N-contiguous). Used for O = P V.
// BM=128, BN=128, BK=16. Same warp layout; B staged as [16][132] (pad 4 ->
// column frag reads conflict-free: bank = 4*(k) + n stride-1 per lane quad).
// ---------------------------------------------------------------------------
__global__ void __launch_bounds__(128) gemm_nn(
    const float* __restrict__ A, const float* __restrict__ B, float* __restrict__ C,
    int lda, int ldb, int ldc, int Kdim,
    long long sA_, long long sB_, long long sC_)
{
    __shared__ __align__(16) uint32_t sAhi[128][20], sAlo[128][20];
    __shared__ __align__(16) uint32_t sBhi[16][132], sBlo[16][132];

    const float* Ag = A + (long long)blockIdx.z * sA_ + (long long)blockIdx.y * 128 * lda;
    const float* Bg = B + (long long)blockIdx.z * sB_ + (long long)blockIdx.x * 128;
    float*       Cg = C + (long long)blockIdx.z * sC_ + (long long)blockIdx.y * 128 * ldc
                        + (long long)blockIdx.x * 128;

    const int tid  = threadIdx.x;
    const int warp = tid >> 5, lane = tid & 31;
    const int wm = (warp >> 1) * 64, wn = (warp & 1) * 64;
    const int lr = lane >> 2, lc = lane & 3;

    const int rs = tid >> 2;           // A rows
    const int cs = (tid & 3) * 4;      // A cols
    const int kb = tid >> 5;           // B k-row component
    const int nb = (tid & 31) * 4;     // B n cols

    float acc[4][8][4] = {};

    for (int k0 = 0; k0 < Kdim; k0 += 16) {
        float4 va[4], vb[4];
#pragma unroll
        for (int p = 0; p < 4; p++) {
            va[p] = *(const float4*)(Ag + (long long)(rs + p * 32) * lda + k0 + cs);
            vb[p] = *(const float4*)(Bg + (long long)(k0 + p * 4 + kb) * ldb + nb);
        }
        __syncthreads();
#pragma unroll
        for (int p = 0; p < 4; p++) {
            uint4 hi, lo;
            split4(va[p], hi, lo);
            *(uint4*)&sAhi[rs + p * 32][cs] = hi;
            *(uint4*)&sAlo[rs + p * 32][cs] = lo;
            split4(vb[p], hi, lo);
            *(uint4*)&sBhi[p * 4 + kb][nb] = hi;
            *(uint4*)&sBlo[p * 4 + kb][nb] = lo;
        }
        __syncthreads();

#pragma unroll
        for (int ks = 0; ks < 16; ks += 8) {
            uint32_t ah[4][4], al[4][4];
#pragma unroll
            for (int mi = 0; mi < 4; mi++) {
                int r0 = wm + mi * 16 + lr;
                ah[mi][0] = sAhi[r0    ][ks + lc    ];  al[mi][0] = sAlo[r0    ][ks + lc    ];
                ah[mi][1] = sAhi[r0 + 8][ks + lc    ];  al[mi][1] = sAlo[r0 + 8][ks + lc    ];
                ah[mi][2] = sAhi[r0    ][ks + lc + 4];  al[mi][2] = sAlo[r0    ][ks + lc + 4];
                ah[mi][3] = sAhi[r0 + 8][ks + lc + 4];  al[mi][3] = sAlo[r0 + 8][ks + lc + 4];
            }
#pragma unroll
            for (int ni = 0; ni < 8; ni++) {
                int n0 = wn + ni * 8 + lr;
                uint32_t bh0 = sBhi[ks + lc    ][n0], bh1 = sBhi[ks + lc + 4][n0];
                uint32_t bl0 = sBlo[ks + lc    ][n0], bl1 = sBlo[ks + lc + 4][n0];
#pragma unroll
                for (int mi = 0; mi < 4; mi++) {
                    mma8(acc[mi][ni], ah[mi][0], ah[mi][1], ah[mi][2], ah[mi][3], bh0, bh1);
                    mma8(acc[mi][ni], ah[mi][0], ah[mi][1], ah[mi][2], ah[mi][3], bl0, bl1);
                    mma8(acc[mi][ni], al[mi][0], al[mi][1], al[mi][2], al[mi][3], bh0, bh1);
                }
            }
        }
    }

#pragma unroll
    for (int mi = 0; mi < 4; mi++)
#pragma unroll
        for (int ni = 0; ni < 8; ni++) {
            int rr = wm + mi * 16 + lr;
            int cc = wn + ni * 8 + lc * 2;
            *(float2*)(Cg + (long long)rr * ldc + cc)       = make_float2(acc[mi][ni][0], acc[mi][ni][1]);
            *(float2*)(Cg + (long long)(rr + 8) * ldc + cc) = make_float2(acc[mi][ni][2], acc[mi][ni][3]);
        }
}

// ---------------------------------------------------------------------------
// Row softmax over SEQ=4096, with /sqrt(H) scale folded in.
// ---------------------------------------------------------------------------
__global__ void __launch_bounds__(256) softmax_kernel(float* __restrict__ S, float scale) {
    long long row = blockIdx.x;
    float* p = S + row * (long long)SEQ;
    const int tid = threadIdx.x;

    float4 v[4];
    float m = -3.4e38f;
#pragma unroll
    for (int i = 0; i < 4; i++) {
        v[i] = ((const float4*)p)[tid + i * 256];
        m = fmaxf(m, fmaxf(fmaxf(v[i].x, v[i].y), fmaxf(v[i].z, v[i].w)));
    }

    __shared__ float red[8];
#pragma unroll
    for (int o = 16; o; o >>= 1) m = fmaxf(m, __shfl_xor_sync(0xffffffffu, m, o));
    if ((tid & 31) == 0) red[tid >> 5] = m;
    __syncthreads();
    m = red[0];
#pragma unroll
    for (int i = 1; i < 8; i++) m = fmaxf(m, red[i]);

    float sum = 0.f;
#pragma unroll
    for (int i = 0; i < 4; i++) {
        v[i].x = __expf((v[i].x - m) * scale);
        v[i].y = __expf((v[i].y - m) * scale);
        v[i].z = __expf((v[i].z - m) * scale);
        v[i].w = __expf((v[i].w - m) * scale);
        sum += (v[i].x + v[i].y) + (v[i].z + v[i].w);
    }
#pragma unroll
    for (int o = 16; o; o >>= 1) sum += __shfl_xor_sync(0xffffffffu, sum, o);
    __syncthreads();
    if ((tid & 31) == 0) red[tid >> 5] = sum;
    __syncthreads();
    float tot = 0.f;
#pragma unroll
    for (int i = 0; i < 8; i++) tot += red[i];
    float inv = 1.0f / tot;

#pragma unroll
    for (int i = 0; i < 4; i++) {
        v[i].x *= inv; v[i].y *= inv; v[i].z *= inv; v[i].w *= inv;
        ((float4*)p)[tid + i * 256] = v[i];
    }
}

// ---------------------------------------------------------------------------
// Launcher
// ---------------------------------------------------------------------------
extern "C" void kernel_launch(void* const* d_in, const int* in_sizes, int n_in,
                              void* d_out, int out_size) {
    const float* x  = (const float*)d_in[0];
    const float* Wq = (const float*)d_in[1];
    const float* Wk = (const float*)d_in[2];
    const float* Wv = (const float*)d_in[3];
    float* out = (float*)d_out;

    float *qp, *sp;
    cudaGetSymbolAddress((void**)&qp, g_qkv);
    cudaGetSymbolAddress((void**)&sp, g_scores);
    float* kp = qp + (long long)BATCH * SEQ * HID;
    float* vp = kp + (long long)BATCH * SEQ * HID;

    dim3 blk(128);

    // 1) QKV projections: y = x W^T   (M=16384, N=512, K=512)
    dim3 gq(HID / 128, (BATCH * SEQ) / 128, 1);
    gemm_nt<<<gq, blk>>>(x, Wq, qp, HID, HID, HID, HID, 0, 0, 0);
    gemm_nt<<<gq, blk>>>(x, Wk, kp, HID, HID, HID, HID, 0, 0, 0);
    gemm_nt<<<gq, blk>>>(x, Wv, vp, HID, HID, HID, HID, 0, 0, 0);

    // 2) S = Q K^T   (batched: M=N=4096, K=512)
    dim3 gs(SEQ / 128, SEQ / 128, BATCH);
    gemm_nt<<<gs, blk>>>(qp, kp, sp, HID, HID, SEQ, HID,
                         (long long)SEQ * HID, (long long)SEQ * HID, (long long)SEQ * SEQ);

    // 3) softmax rows with 1/sqrt(H) scale
    softmax_kernel<<<BATCH * SEQ, 256>>>(sp, 0.044194173824159216f);

    // 4) O = P V   (M=4096, N=512, K=4096, batched)
    dim3 gp(HID / 128, SEQ / 128, BATCH);
    gemm_nn<<<gp, blk>>>(sp, vp, out, SEQ, HID, HID, SEQ,
                         (long long)SEQ * SEQ, (long long)SEQ * HID, (long long)SEQ * HID);
}

// round 4
// speedup vs baseline: 3.4094x; 1.7124x over previous
#include <cuda_runtime.h>
#include <cuda_bf16.h>
#include <cstdint>

#define HID  512
#define BATCH 4
#define SEQ  4096

// Scratch (static device globals; allocation-free per harness rules)
// q | k | vt  (vt stored transposed per batch: [HID][SEQ])
__device__ float g_qkv[(size_t)3 * BATCH * SEQ * HID];          // 96 MB
__device__ float g_scores[(size_t)BATCH * SEQ * SEQ];           // 256 MB

// ---------------------------------------------------------------------------
// bf16 split helpers: f = hi + lo with hi,lo bf16; pack pairs into bf16x2 words
// ---------------------------------------------------------------------------
__device__ __forceinline__ void split2(float f0, float f1, uint32_t& hi, uint32_t& lo) {
    // hi = {bf16(f1) high, bf16(f0) low}
    asm("cvt.rn.bf16x2.f32 %0, %2, %1;" : "=r"(hi) : "f"(f0), "f"(f1));
    float h0 = __uint_as_float(hi << 16);
    float h1 = __uint_as_float(hi & 0xffff0000u);
    float l0 = f0 - h0;
    float l1 = f1 - h1;
    asm("cvt.rn.bf16x2.f32 %0, %2, %1;" : "=r"(lo) : "f"(l0), "f"(l1));
}

__device__ __forceinline__ void mma16(float c[4],
                                      uint32_t a0, uint32_t a1, uint32_t a2, uint32_t a3,
                                      uint32_t b0, uint32_t b1) {
    asm volatile(
        "mma.sync.aligned.m16n8k16.row.col.f32.bf16.bf16.f32 "
        "{%0,%1,%2,%3}, {%4,%5,%6,%7}, {%8,%9}, {%0,%1,%2,%3};\n"
        : "+f"(c[0]), "+f"(c[1]), "+f"(c[2]), "+f"(c[3])
        : "r"(a0), "r"(a1), "r"(a2), "r"(a3), "r"(b0), "r"(b1));
}

// ---------------------------------------------------------------------------
// GEMM NT (bf16 3-split): C[m,n] = sum_k A[m,k] * B[n,k]  (both K-major fp32)
// BM=128, BN=128, BK=16 floats (= 8 bf16x2 words). 128 threads = 4 warps
// (2x2), warp tile 64x64. Shared: [row][12] uint32, conflict-free frag reads.
// tout=1: write C transposed per batch (used for the V projection -> Vt).
// ---------------------------------------------------------------------------
__global__ void __launch_bounds__(128) gemm_nt(
    const float* __restrict__ A, const float* __restrict__ B, float* __restrict__ C,
    int lda, int ldb, int ldc, int Kdim,
    long long sA_, long long sB_, long long sC_, int tout)
{
    __shared__ __align__(16) uint32_t sAhi[128][12], sAlo[128][12];
    __shared__ __align__(16) uint32_t sBhi[128][12], sBlo[128][12];

    const float* Ag = A + (long long)blockIdx.z * sA_ + (long long)blockIdx.y * 128 * lda;
    const float* Bg = B + (long long)blockIdx.z * sB_ + (long long)blockIdx.x * 128 * ldb;

    const int tid  = threadIdx.x;
    const int warp = tid >> 5, lane = tid & 31;
    const int wm = (warp >> 1) * 64, wn = (warp & 1) * 64;
    const int lr = lane >> 2, lc = lane & 3;

    // staging coords: thread covers rows p*32 + (tid>>2), float cols (tid&3)*4
    const int rs = tid >> 2;
    const int cs = (tid & 3) * 4;        // float col
    const int cw = (tid & 3) * 2;        // bf16x2 word col

    float acc[4][8][4] = {};

    for (int k0 = 0; k0 < Kdim; k0 += 16) {
        float4 va[4], vb[4];
#pragma unroll
        for (int p = 0; p < 4; p++) {
            va[p] = *(const float4*)(Ag + (long long)(rs + p * 32) * lda + k0 + cs);
            vb[p] = *(const float4*)(Bg + (long long)(rs + p * 32) * ldb + k0 + cs);
        }
        __syncthreads();
#pragma unroll
        for (int p = 0; p < 4; p++) {
            uint32_t h0, l0, h1, l1;
            split2(va[p].x, va[p].y, h0, l0);
            split2(va[p].z, va[p].w, h1, l1);
            sAhi[rs + p * 32][cw]     = h0;  sAhi[rs + p * 32][cw + 1] = h1;
            sAlo[rs + p * 32][cw]     = l0;  sAlo[rs + p * 32][cw + 1] = l1;
            split2(vb[p].x, vb[p].y, h0, l0);
            split2(vb[p].z, vb[p].w, h1, l1);
            sBhi[rs + p * 32][cw]     = h0;  sBhi[rs + p * 32][cw + 1] = h1;
            sBlo[rs + p * 32][cw]     = l0;  sBlo[rs + p * 32][cw + 1] = l1;
        }
        __syncthreads();

        // one k16 step covers the whole BK=16 stage
        uint32_t ah[4][4], al[4][4];
#pragma unroll
        for (int mi = 0; mi < 4; mi++) {
            int r0 = wm + mi * 16 + lr;
            ah[mi][0] = sAhi[r0    ][lc    ];  al[mi][0] = sAlo[r0    ][lc    ];
            ah[mi][1] = sAhi[r0 + 8][lc    ];  al[mi][1] = sAlo[r0 + 8][lc    ];
            ah[mi][2] = sAhi[r0    ][lc + 4];  al[mi][2] = sAlo[r0    ][lc + 4];
            ah[mi][3] = sAhi[r0 + 8][lc + 4];  al[mi][3] = sAlo[r0 + 8][lc + 4];
        }
#pragma unroll
        for (int ni = 0; ni < 8; ni++) {
            int n0 = wn + ni * 8 + lr;
            uint32_t bh0 = sBhi[n0][lc], bh1 = sBhi[n0][lc + 4];
            uint32_t bl0 = sBlo[n0][lc], bl1 = sBlo[n0][lc + 4];
#pragma unroll
            for (int mi = 0; mi < 4; mi++) {
                mma16(acc[mi][ni], ah[mi][0], ah[mi][1], ah[mi][2], ah[mi][3], bh0, bh1);
                mma16(acc[mi][ni], ah[mi][0], ah[mi][1], ah[mi][2], ah[mi][3], bl0, bl1);
                mma16(acc[mi][ni], al[mi][0], al[mi][1], al[mi][2], al[mi][3], bh0, bh1);
            }
        }
    }

    if (!tout) {
        float* Cg = C + (long long)blockIdx.z * sC_ + (long long)blockIdx.y * 128 * ldc
                      + (long long)blockIdx.x * 128;
#pragma unroll
        for (int mi = 0; mi < 4; mi++)
#pragma unroll
            for (int ni = 0; ni < 8; ni++) {
                int rr = wm + mi * 16 + lr;
                int cc = wn + ni * 8 + lc * 2;
                *(float2*)(Cg + (long long)rr * ldc + cc)       = make_float2(acc[mi][ni][0], acc[mi][ni][1]);
                *(float2*)(Cg + (long long)(rr + 8) * ldc + cc) = make_float2(acc[mi][ni][2], acc[mi][ni][3]);
            }
    } else {
        // transposed write: global row R = (b,s), col h  ->  C[b][h][s]
#pragma unroll
        for (int mi = 0; mi < 4; mi++)
#pragma unroll
            for (int ni = 0; ni < 8; ni++) {
                int R  = blockIdx.y * 128 + wm + mi * 16 + lr;
                int hc = blockIdx.x * 128 + wn + ni * 8 + lc * 2;
                int b  = R >> 12, s = R & (SEQ - 1);
                float* base = C + (long long)b * HID * SEQ;
                base[(long long)hc * SEQ + s]           = acc[mi][ni][0];
                base[(long long)(hc + 1) * SEQ + s]     = acc[mi][ni][1];
                base[(long long)hc * SEQ + s + 8]       = acc[mi][ni][2];
                base[(long long)(hc + 1) * SEQ + s + 8] = acc[mi][ni][3];
            }
    }
}

// ---------------------------------------------------------------------------
// Row softmax over SEQ=4096, with /sqrt(H) scale folded in.
// ---------------------------------------------------------------------------
__global__ void __launch_bounds__(256) softmax_kernel(float* __restrict__ S, float scale) {
    long long row = blockIdx.x;
    float* p = S + row * (long long)SEQ;
    const int tid = threadIdx.x;

    float4 v[4];
    float m = -3.4e38f;
#pragma unroll
    for (int i = 0; i < 4; i++) {
        v[i] = ((const float4*)p)[tid + i * 256];
        m = fmaxf(m, fmaxf(fmaxf(v[i].x, v[i].y), fmaxf(v[i].z, v[i].w)));
    }

    __shared__ float red[8];
#pragma unroll
    for (int o = 16; o; o >>= 1) m = fmaxf(m, __shfl_xor_sync(0xffffffffu, m, o));
    if ((tid & 31) == 0) red[tid >> 5] = m;
    __syncthreads();
    m = red[0];
#pragma unroll
    for (int i = 1; i < 8; i++) m = fmaxf(m, red[i]);

    float sum = 0.f;
#pragma unroll
    for (int i = 0; i < 4; i++) {
        v[i].x = __expf((v[i].x - m) * scale);
        v[i].y = __expf((v[i].y - m) * scale);
        v[i].z = __expf((v[i].z - m) * scale);
        v[i].w = __expf((v[i].w - m) * scale);
        sum += (v[i].x + v[i].y) + (v[i].z + v[i].w);
    }
#pragma unroll
    for (int o = 16; o; o >>= 1) sum += __shfl_xor_sync(0xffffffffu, sum, o);
    __syncthreads();
    if ((tid & 31) == 0) red[tid >> 5] = sum;
    __syncthreads();
    float tot = 0.f;
#pragma unroll
    for (int i = 0; i < 8; i++) tot += red[i];
    float inv = 1.0f / tot;

#pragma unroll
    for (int i = 0; i < 4; i++) {
        v[i].x *= inv; v[i].y *= inv; v[i].z *= inv; v[i].w *= inv;
        ((float4*)p)[tid + i * 256] = v[i];
    }
}

// ---------------------------------------------------------------------------
// Launcher
// ---------------------------------------------------------------------------
extern "C" void kernel_launch(void* const* d_in, const int* in_sizes, int n_in,
                              void* d_out, int out_size) {
    const float* x  = (const float*)d_in[0];
    const float* Wq = (const float*)d_in[1];
    const float* Wk = (const float*)d_in[2];
    const float* Wv = (const float*)d_in[3];
    float* out = (float*)d_out;

    float *qp, *sp;
    cudaGetSymbolAddress((void**)&qp, g_qkv);
    cudaGetSymbolAddress((void**)&sp, g_scores);
    float* kp  = qp + (long long)BATCH * SEQ * HID;
    float* vtp = kp + (long long)BATCH * SEQ * HID;     // transposed V: [b][h][s]

    dim3 blk(128);

    // 1) QKV projections: y = x W^T  (M=16384, N=512, K=512); V written transposed
    dim3 gq(HID / 128, (BATCH * SEQ) / 128, 1);
    gemm_nt<<<gq, blk>>>(x, Wq, qp,  HID, HID, HID, HID, 0, 0, 0, 0);
    gemm_nt<<<gq, blk>>>(x, Wk, kp,  HID, HID, HID, HID, 0, 0, 0, 0);
    gemm_nt<<<gq, blk>>>(x, Wv, vtp, HID, HID, HID, HID, 0, 0, 0, 1);

    // 2) S = Q K^T  (batched: M=N=4096, K=512)
    dim3 gs(SEQ / 128, SEQ / 128, BATCH);
    gemm_nt<<<gs, blk>>>(qp, kp, sp, HID, HID, SEQ, HID,
                         (long long)SEQ * HID, (long long)SEQ * HID,
                         (long long)SEQ * SEQ, 0);

    // 3) softmax rows with 1/sqrt(H) scale
    softmax_kernel<<<BATCH * SEQ, 256>>>(sp, 0.044194173824159216f);

    // 4) O = P Vt^T  (NT: M=4096, N=512, K=4096, batched)
    dim3 gp(HID / 128, SEQ / 128, BATCH);
    gemm_nt<<<gp, blk>>>(sp, vtp, out, SEQ, SEQ, HID, SEQ,
                         (long long)SEQ * SEQ, (long long)HID * SEQ,
                         (long long)SEQ * HID, 0);
}

// round 5
// speedup vs baseline: 3.7482x; 1.0994x over previous
#include <cuda_runtime.h>
#include <cuda_bf16.h>
#include <cstdint>

#define HID  512
#define BATCH 4
#define SEQ  4096

// Scratch (static device globals; allocation-free per harness rules)
// q | k | vt  (vt stored transposed per batch: [HID][SEQ])
__device__ float g_qkv[(size_t)3 * BATCH * SEQ * HID];          // 96 MB
__device__ float g_scores[(size_t)BATCH * SEQ * SEQ];           // 256 MB

// ---------------------------------------------------------------------------
// bf16 split helpers: f = hi + lo with hi,lo bf16; pack pairs into bf16x2 words
// ---------------------------------------------------------------------------
__device__ __forceinline__ void split2(float f0, float f1, uint32_t& hi, uint32_t& lo) {
    asm("cvt.rn.bf16x2.f32 %0, %2, %1;" : "=r"(hi) : "f"(f0), "f"(f1));
    float h0 = __uint_as_float(hi << 16);
    float h1 = __uint_as_float(hi & 0xffff0000u);
    float l0 = f0 - h0;
    float l1 = f1 - h1;
    asm("cvt.rn.bf16x2.f32 %0, %2, %1;" : "=r"(lo) : "f"(l0), "f"(l1));
}

__device__ __forceinline__ void mma16(float c[4],
                                      uint32_t a0, uint32_t a1, uint32_t a2, uint32_t a3,
                                      uint32_t b0, uint32_t b1) {
    asm volatile(
        "mma.sync.aligned.m16n8k16.row.col.f32.bf16.bf16.f32 "
        "{%0,%1,%2,%3}, {%4,%5,%6,%7}, {%8,%9}, {%0,%1,%2,%3};\n"
        : "+f"(c[0]), "+f"(c[1]), "+f"(c[2]), "+f"(c[3])
        : "r"(a0), "r"(a1), "r"(a2), "r"(a3), "r"(b0), "r"(b1));
}

// ---------------------------------------------------------------------------
// GEMM NT (bf16 3-split, double-buffered): C[m,n] = sum_k A[m,k] * B[n,k]
// BM=128, BN=128, BK=16 floats. 128 threads = 4 warps (2x2), warp tile 64x64.
// Dynamic smem 48KB: 2 buffers x (A hi/lo + B hi/lo) in [row][12] layout.
// One __syncthreads per K-stage; gmem prefetch overlaps MMA compute.
// tout=1: write C transposed per batch (used for the V projection -> Vt).
// ---------------------------------------------------------------------------
#define STG 1536   // uint32 per buffer per array: 128*12

__global__ void __launch_bounds__(128) gemm_nt(
    const float* __restrict__ A, const float* __restrict__ B, float* __restrict__ C,
    int lda, int ldb, int ldc, int Kdim,
    long long sA_, long long sB_, long long sC_, int tout)
{
    extern __shared__ __align__(16) uint32_t dsm[];
    uint32_t* sAhi = dsm;
    uint32_t* sAlo = dsm + 2 * STG;
    uint32_t* sBhi = dsm + 4 * STG;
    uint32_t* sBlo = dsm + 6 * STG;

    const float* Ag = A + (long long)blockIdx.z * sA_ + (long long)blockIdx.y * 128 * lda;
    const float* Bg = B + (long long)blockIdx.z * sB_ + (long long)blockIdx.x * 128 * ldb;

    const int tid  = threadIdx.x;
    const int warp = tid >> 5, lane = tid & 31;
    const int wm = (warp >> 1) * 64, wn = (warp & 1) * 64;
    const int lr = lane >> 2, lc = lane & 3;

    // staging coords: thread covers rows p*32 + (tid>>2), float cols (tid&3)*4
    const int rs = tid >> 2;
    const int cs = (tid & 3) * 4;        // float col
    const int cw = (tid & 3) * 2;        // bf16x2 word col

    float acc[4][8][4] = {};

    float4 va[4], vb[4];
    auto load_gmem = [&](int k0, float4 a[4], float4 b[4]) {
#pragma unroll
        for (int p = 0; p < 4; p++) {
            a[p] = *(const float4*)(Ag + (long long)(rs + p * 32) * lda + k0 + cs);
            b[p] = *(const float4*)(Bg + (long long)(rs + p * 32) * ldb + k0 + cs);
        }
    };
    auto store_smem = [&](int buf, const float4 a[4], const float4 b[4]) {
        uint32_t* pAh = sAhi + buf * STG;
        uint32_t* pAl = sAlo + buf * STG;
        uint32_t* pBh = sBhi + buf * STG;
        uint32_t* pBl = sBlo + buf * STG;
#pragma unroll
        for (int p = 0; p < 4; p++) {
            int ro = (rs + p * 32) * 12;
            uint32_t h0, l0, h1, l1;
            split2(a[p].x, a[p].y, h0, l0);
            split2(a[p].z, a[p].w, h1, l1);
            pAh[ro + cw] = h0;  pAh[ro + cw + 1] = h1;
            pAl[ro + cw] = l0;  pAl[ro + cw + 1] = l1;
            split2(b[p].x, b[p].y, h0, l0);
            split2(b[p].z, b[p].w, h1, l1);
            pBh[ro + cw] = h0;  pBh[ro + cw + 1] = h1;
            pBl[ro + cw] = l0;  pBl[ro + cw + 1] = l1;
        }
    };
    auto compute = [&](int buf) {
        const uint32_t* pAh = sAhi + buf * STG;
        const uint32_t* pAl = sAlo + buf * STG;
        const uint32_t* pBh = sBhi + buf * STG;
        const uint32_t* pBl = sBlo + buf * STG;
        uint32_t ah[4][4], al[4][4];
#pragma unroll
        for (int mi = 0; mi < 4; mi++) {
            int r0 = (wm + mi * 16 + lr) * 12;
            ah[mi][0] = pAh[r0       + lc    ];  al[mi][0] = pAl[r0       + lc    ];
            ah[mi][1] = pAh[r0 + 96  + lc    ];  al[mi][1] = pAl[r0 + 96  + lc    ];
            ah[mi][2] = pAh[r0       + lc + 4];  al[mi][2] = pAl[r0       + lc + 4];
            ah[mi][3] = pAh[r0 + 96  + lc + 4];  al[mi][3] = pAl[r0 + 96  + lc + 4];
        }
#pragma unroll
        for (int ni = 0; ni < 8; ni++) {
            int n0 = (wn + ni * 8 + lr) * 12;
            uint32_t bh0 = pBh[n0 + lc], bh1 = pBh[n0 + lc + 4];
            uint32_t bl0 = pBl[n0 + lc], bl1 = pBl[n0 + lc + 4];
#pragma unroll
            for (int mi = 0; mi < 4; mi++) {
                mma16(acc[mi][ni], ah[mi][0], ah[mi][1], ah[mi][2], ah[mi][3], bh0, bh1);
                mma16(acc[mi][ni], ah[mi][0], ah[mi][1], ah[mi][2], ah[mi][3], bl0, bl1);
                mma16(acc[mi][ni], al[mi][0], al[mi][1], al[mi][2], al[mi][3], bh0, bh1);
            }
        }
    };

    // prologue
    load_gmem(0, va, vb);
    store_smem(0, va, vb);
    __syncthreads();

    int buf = 0;
    for (int k0 = 0; k0 < Kdim; k0 += 16) {
        bool more = (k0 + 16) < Kdim;
        if (more) load_gmem(k0 + 16, va, vb);   // prefetch overlaps compute
        compute(buf);
        if (more) {
            store_smem(buf ^ 1, va, vb);
            __syncthreads();
            buf ^= 1;
        }
    }

    if (!tout) {
        float* Cg = C + (long long)blockIdx.z * sC_ + (long long)blockIdx.y * 128 * ldc
                      + (long long)blockIdx.x * 128;
#pragma unroll
        for (int mi = 0; mi < 4; mi++)
#pragma unroll
            for (int ni = 0; ni < 8; ni++) {
                int rr = wm + mi * 16 + lr;
                int cc = wn + ni * 8 + lc * 2;
                *(float2*)(Cg + (long long)rr * ldc + cc)       = make_float2(acc[mi][ni][0], acc[mi][ni][1]);
                *(float2*)(Cg + (long long)(rr + 8) * ldc + cc) = make_float2(acc[mi][ni][2], acc[mi][ni][3]);
            }
    } else {
        // transposed write: global row R = (b,s), col h  ->  C[b][h][s]
#pragma unroll
        for (int mi = 0; mi < 4; mi++)
#pragma unroll
            for (int ni = 0; ni < 8; ni++) {
                int R  = blockIdx.y * 128 + wm + mi * 16 + lr;
                int hc = blockIdx.x * 128 + wn + ni * 8 + lc * 2;
                int b  = R >> 12, s = R & (SEQ - 1);
                float* base = C + (long long)b * HID * SEQ;
                base[(long long)hc * SEQ + s]           = acc[mi][ni][0];
                base[(long long)(hc + 1) * SEQ + s]     = acc[mi][ni][1];
                base[(long long)hc * SEQ + s + 8]       = acc[mi][ni][2];
                base[(long long)(hc + 1) * SEQ + s + 8] = acc[mi][ni][3];
            }
    }
}

// ---------------------------------------------------------------------------
// Row softmax over SEQ=4096, with /sqrt(H) scale folded in.
// ---------------------------------------------------------------------------
__global__ void __launch_bounds__(256) softmax_kernel(float* __restrict__ S, float scale) {
    long long row = blockIdx.x;
    float* p = S + row * (long long)SEQ;
    const int tid = threadIdx.x;

    float4 v[4];
    float m = -3.4e38f;
#pragma unroll
    for (int i = 0; i < 4; i++) {
        v[i] = ((const float4*)p)[tid + i * 256];
        m = fmaxf(m, fmaxf(fmaxf(v[i].x, v[i].y), fmaxf(v[i].z, v[i].w)));
    }

    __shared__ float red[8];
#pragma unroll
    for (int o = 16; o; o >>= 1) m = fmaxf(m, __shfl_xor_sync(0xffffffffu, m, o));
    if ((tid & 31) == 0) red[tid >> 5] = m;
    __syncthreads();
    m = red[0];
#pragma unroll
    for (int i = 1; i < 8; i++) m = fmaxf(m, red[i]);

    float sum = 0.f;
#pragma unroll
    for (int i = 0; i < 4; i++) {
        v[i].x = __expf((v[i].x - m) * scale);
        v[i].y = __expf((v[i].y - m) * scale);
        v[i].z = __expf((v[i].z - m) * scale);
        v[i].w = __expf((v[i].w - m) * scale);
        sum += (v[i].x + v[i].y) + (v[i].z + v[i].w);
    }
#pragma unroll
    for (int o = 16; o; o >>= 1) sum += __shfl_xor_sync(0xffffffffu, sum, o);
    __syncthreads();
    if ((tid & 31) == 0) red[tid >> 5] = sum;
    __syncthreads();
    float tot = 0.f;
#pragma unroll
    for (int i = 0; i < 8; i++) tot += red[i];
    float inv = 1.0f / tot;

#pragma unroll
    for (int i = 0; i < 4; i++) {
        v[i].x *= inv; v[i].y *= inv; v[i].z *= inv; v[i].w *= inv;
        ((float4*)p)[tid + i * 256] = v[i];
    }
}

// ---------------------------------------------------------------------------
// Launcher
// ---------------------------------------------------------------------------
#define GEMM_SMEM 49152

extern "C" void kernel_launch(void* const* d_in, const int* in_sizes, int n_in,
                              void* d_out, int out_size) {
    const float* x  = (const float*)d_in[0];
    const float* Wq = (const float*)d_in[1];
    const float* Wk = (const float*)d_in[2];
    const float* Wv = (const float*)d_in[3];
    float* out = (float*)d_out;

    float *qp, *sp;
    cudaGetSymbolAddress((void**)&qp, g_qkv);
    cudaGetSymbolAddress((void**)&sp, g_scores);
    float* kp  = qp + (long long)BATCH * SEQ * HID;
    float* vtp = kp + (long long)BATCH * SEQ * HID;     // transposed V: [b][h][s]

    cudaFuncSetAttribute(gemm_nt, cudaFuncAttributeMaxDynamicSharedMemorySize, GEMM_SMEM);

    dim3 blk(128);

    // 1) QKV projections: y = x W^T  (M=16384, N=512, K=512); V written transposed
    dim3 gq(HID / 128, (BATCH * SEQ) / 128, 1);
    gemm_nt<<<gq, blk, GEMM_SMEM>>>(x, Wq, qp,  HID, HID, HID, HID, 0, 0, 0, 0);
    gemm_nt<<<gq, blk, GEMM_SMEM>>>(x, Wk, kp,  HID, HID, HID, HID, 0, 0, 0, 0);
    gemm_nt<<<gq, blk, GEMM_SMEM>>>(x, Wv, vtp, HID, HID, HID, HID, 0, 0, 0, 1);

    // 2) S = Q K^T  (batched: M=N=4096, K=512)
    dim3 gs(SEQ / 128, SEQ / 128, BATCH);
    gemm_nt<<<gs, blk, GEMM_SMEM>>>(qp, kp, sp, HID, HID, SEQ, HID,
                                    (long long)SEQ * HID, (long long)SEQ * HID,
                                    (long long)SEQ * SEQ, 0);

    // 3) softmax rows with 1/sqrt(H) scale
    softmax_kernel<<<BATCH * SEQ, 256>>>(sp, 0.044194173824159216f);

    // 4) O = P Vt^T  (NT: M=4096, N=512, K=4096, batched)
    dim3 gp(HID / 128, SEQ / 128, BATCH);
    gemm_nt<<<gp, blk, GEMM_SMEM>>>(sp, vtp, out, SEQ, SEQ, HID, SEQ,
                                    (long long)SEQ * SEQ, (long long)HID * SEQ,
                                    (long long)SEQ * HID, 0);
}